// round 15
// baseline (speedup 1.0000x reference)
#include <cuda_runtime.h>
#include <cuda_bf16.h>
#include <math.h>
#include <stdint.h>

typedef unsigned int u32;

#define TPB 512

// ---- smem layout (floats) ----
#define LDH   128
#define LDS_  266            // S row stride (q/ff1a 0..127 | v/ff1b 134..261)
#define LDKT  66
#define LDG_  134

#define OFF_H   0            // h [65][128] = 8320 f
#define OFF_S   8320         // S [65][266] = 17290 f
#define OFF_A   25612        // A-stage: Ah,Al 2x(65 rows x 272B) = 8840 f ; aliased: kT [128][66]
#define A_TERM_B 17680       // bytes per A term (65*272)
#define OFF_B   34452        // B-stage: Bh,Bl 2x(128 rows x 272B) = 17408 f ; aliased: G, scratch, x
#define B_TERM_B 34816       // bytes per B term (128*272)
#define SMEM_FLOATS 51860    // 207,440 B

// pre-split weights, padded-row layout identical to smem stage image:
// [layer][tile][hi/lo][n=128][136 bf16 (272B row, 128 data + pad)]
// tiles: 0=Wq 1=Wv 2=Wk 3=Wout 4=ff1a 5=ff1b 6=ff2c0 7=ff2c1
__device__ __align__(16) __nv_bfloat16 g_wsplit[4][8][2][128 * 136];

__global__ void prep_kernel(const float* __restrict__ qkv_w,
                            const float* __restrict__ out_w,
                            const float* __restrict__ ff1_w,
                            const float* __restrict__ ff2_w)
{
    int e = blockIdx.x * blockDim.x + threadIdx.x;     // 524288 total
    int layer = e >> 17;
    int r     = e & 131071;
    int tile  = r >> 14;
    int r2    = r & 16383;
    int n = r2 >> 7, k = r2 & 127;
    float w;
    if (tile == 0)      w = qkv_w[layer * 49152 + n * 128 + k];                    // Wq
    else if (tile == 1) w = qkv_w[layer * 49152 + (256 + n) * 128 + k];            // Wv
    else if (tile == 2) w = qkv_w[layer * 49152 + (128 + n) * 128 + k];            // Wk
    else if (tile == 3) w = out_w[layer * 16384 + n * 128 + k];
    else if (tile < 6)  w = ff1_w[layer * 32768 + ((tile - 4) * 128 + n) * 128 + k];
    else                w = ff2_w[layer * 32768 + n * 256 + (tile - 6) * 128 + k];
    __nv_bfloat16 hi = __float2bfloat16_rn(w);
    __nv_bfloat16 lo = __float2bfloat16_rn(w - __bfloat162float(hi));
    g_wsplit[layer][tile][0][n * 136 + k] = hi;
    g_wsplit[layer][tile][1][n * 136 + k] = lo;
}

// ---- helpers ----
__device__ __forceinline__ u32 smem_u32(const void* p) {
    u32 a;
    asm("{ .reg .u64 t; cvta.to.shared.u64 t, %1; cvt.u32.u64 %0, t; }" : "=r"(a) : "l"(p));
    return a;
}
__device__ __forceinline__ float4 ld4(const float* p) { return *reinterpret_cast<const float4*>(p); }
__device__ __forceinline__ float warp_sum(float v) {
#pragma unroll
    for (int o = 16; o > 0; o >>= 1) v += __shfl_xor_sync(0xffffffffu, v, o);
    return v;
}
__device__ __forceinline__ float warp_max(float v) {
#pragma unroll
    for (int o = 16; o > 0; o >>= 1) v = fmaxf(v, __shfl_xor_sync(0xffffffffu, v, o));
    return v;
}
__device__ __forceinline__ void ldm4(u32* r, u32 addr) {
    asm volatile("ldmatrix.sync.aligned.m8n8.x4.shared.b16 {%0,%1,%2,%3}, [%4];"
                 : "=r"(r[0]), "=r"(r[1]), "=r"(r[2]), "=r"(r[3]) : "r"(addr));
}
__device__ __forceinline__ void mma16816(float* d, const u32* a, u32 b0, u32 b1) {
    asm volatile("mma.sync.aligned.m16n8k16.row.col.f32.bf16.bf16.f32 "
                 "{%0,%1,%2,%3}, {%4,%5,%6,%7}, {%8,%9}, {%0,%1,%2,%3};"
                 : "+f"(d[0]), "+f"(d[1]), "+f"(d[2]), "+f"(d[3])
                 : "r"(a[0]), "r"(a[1]), "r"(a[2]), "r"(a[3]), "r"(b0), "r"(b1));
}

// stage Bh+Bl (contiguous 69632 B = 4352 uint4) from pre-split global into B region
__device__ __forceinline__ void stage_B(const __nv_bfloat16* __restrict__ src,
                                        float* __restrict__ Breg, int tid)
{
    const uint4* s = reinterpret_cast<const uint4*>(src);
    uint4*       d = reinterpret_cast<uint4*>(Breg);
    for (int i = tid; i < 4352; i += TPB) d[i] = s[i];
}

// convert A (65 x 128 fp32, row stride lda) -> Ah + Al bf16 padded tiles
__device__ __forceinline__ void convert_A(const float* __restrict__ src, int lda,
                                          char* __restrict__ Ast, int tid)
{
    for (int idx = tid; idx < 4160; idx += TPB) {     // 65 rows * 64 k-pairs
        int row = idx >> 6, kp = idx & 63;
        float2 v = *reinterpret_cast<const float2*>(src + row * lda + kp * 2);
        __nv_bfloat16 h0 = __float2bfloat16_rn(v.x);
        __nv_bfloat16 h1 = __float2bfloat16_rn(v.y);
        __nv_bfloat16 l0 = __float2bfloat16_rn(v.x - __bfloat162float(h0));
        __nv_bfloat16 l1 = __float2bfloat16_rn(v.y - __bfloat162float(h1));
        char* p = Ast + row * 272 + kp * 4;
        *reinterpret_cast<u32*>(p) =
            ((u32)__bfloat16_as_ushort(h1) << 16) | (u32)__bfloat16_as_ushort(h0);
        *reinterpret_cast<u32*>(p + A_TERM_B) =
            ((u32)__bfloat16_as_ushort(l1) << 16) | (u32)__bfloat16_as_ushort(l0);
    }
}

// 3-term 65x128x128 GEMM tile: rows 0-63 via HMMA (warp m16 x n32), row 64 via gemv.
// Fragment-reuse form: per kstep load aH,aL,bH,bL once, issue 12 MMAs.
__device__ void gemm_tile(const float* __restrict__ Afp, int lda,
                          u32 aB, u32 bB, const float* __restrict__ smB,
                          float (&d)[4][4], float (&g)[8], int lane, int wid)
{
    const int mg = wid >> 2, ng = wid & 3;
    const u32 aAddr = aB + (u32)((mg * 16 + (lane & 15)) * 272 + ((lane >> 4) << 4));
    const u32 bAddr = bB + (u32)((ng * 32 + ((lane >> 4) << 3) + (lane & 7)) * 272
                                 + (((lane >> 3) & 1) << 4));
#pragma unroll
    for (int ks = 0; ks < 8; ++ks) {
        u32 aH[4], aL[4], pH[4], qH[4], pL[4], qL[4];
        ldm4(aH, aAddr + ks * 32);
        ldm4(pH, bAddr + ks * 32);
        ldm4(qH, bAddr + 16 * 272 + ks * 32);
        mma16816(d[0], aH, pH[0], pH[1]);
        mma16816(d[1], aH, pH[2], pH[3]);
        mma16816(d[2], aH, qH[0], qH[1]);
        mma16816(d[3], aH, qH[2], qH[3]);
        ldm4(pL, bAddr + B_TERM_B + ks * 32);
        ldm4(qL, bAddr + B_TERM_B + 16 * 272 + ks * 32);
        mma16816(d[0], aH, pL[0], pL[1]);
        mma16816(d[1], aH, pL[2], pL[3]);
        mma16816(d[2], aH, qL[0], qL[1]);
        mma16816(d[3], aH, qL[2], qL[3]);
        ldm4(aL, aAddr + A_TERM_B + ks * 32);
        mma16816(d[0], aL, pH[0], pH[1]);
        mma16816(d[1], aL, pH[2], pH[3]);
        mma16816(d[2], aL, qH[0], qH[1]);
        mma16816(d[3], aL, qH[2], qH[3]);
    }
    // row 64 gemv (B = hi + lo)
    const float* A64 = Afp + 64 * lda;
    const __nv_bfloat16* BH = reinterpret_cast<const __nv_bfloat16*>(smB);
    const __nv_bfloat16* BL = reinterpret_cast<const __nv_bfloat16*>(
                                  reinterpret_cast<const char*>(smB) + B_TERM_B);
    float a0 = A64[lane], a1 = A64[lane + 32], a2 = A64[lane + 64], a3 = A64[lane + 96];
#pragma unroll
    for (int jj = 0; jj < 8; ++jj) {
        int n = wid * 8 + jj;
        const __nv_bfloat16* rh = BH + n * 136;
        const __nv_bfloat16* rl = BL + n * 136;
        float s;
        s = fmaf(a0, __bfloat162float(rh[lane])      + __bfloat162float(rl[lane]),      0.f);
        s = fmaf(a1, __bfloat162float(rh[lane + 32]) + __bfloat162float(rl[lane + 32]), s);
        s = fmaf(a2, __bfloat162float(rh[lane + 64]) + __bfloat162float(rl[lane + 64]), s);
        s = fmaf(a3, __bfloat162float(rh[lane + 96]) + __bfloat162float(rl[lane + 96]), s);
        g[jj] += s;
    }
}

__device__ __forceinline__ void zero_acc(float (&d)[4][4], float (&g)[8]) {
#pragma unroll
    for (int i = 0; i < 4; ++i)
#pragma unroll
        for (int j = 0; j < 4; ++j) d[i][j] = 0.f;
#pragma unroll
    for (int j = 0; j < 8; ++j) g[j] = 0.f;
}

template<int RELU, int TRANS>
__device__ void epilogue(float (&d)[4][4], float (&g)[8],
                         const float* __restrict__ bias,
                         float* __restrict__ Out, int ldo, int lane, int wid)
{
    const int mg = wid >> 2, ng = wid & 3;
    const int r0 = mg * 16 + (lane >> 2);
    const int c0 = ng * 32 + (lane & 3) * 2;
#pragma unroll
    for (int nt = 0; nt < 4; ++nt) {
        int c = c0 + nt * 8;
        float b0 = bias[c], b1 = bias[c + 1];
        float v0 = d[nt][0] + b0, v1 = d[nt][1] + b1;
        float v2 = d[nt][2] + b0, v3 = d[nt][3] + b1;
        if (RELU) {
            v0 = fmaxf(v0, 0.f); v1 = fmaxf(v1, 0.f);
            v2 = fmaxf(v2, 0.f); v3 = fmaxf(v3, 0.f);
        }
        if (TRANS) {
            Out[c * ldo + r0]           = v0;
            Out[(c + 1) * ldo + r0]     = v1;
            Out[c * ldo + r0 + 8]       = v2;
            Out[(c + 1) * ldo + r0 + 8] = v3;
        } else {
            Out[r0 * ldo + c]           = v0;
            Out[r0 * ldo + c + 1]       = v1;
            Out[(r0 + 8) * ldo + c]     = v2;
            Out[(r0 + 8) * ldo + c + 1] = v3;
        }
    }
#pragma unroll
    for (int jj = 0; jj < 8; ++jj) {
        float s = warp_sum(g[jj]);
        if (lane == jj) {
            int j = wid * 8 + jj;
            float v = s + bias[j];
            if (RELU) v = fmaxf(v, 0.f);
            if (TRANS) Out[j * ldo + 64] = v;
            else       Out[64 * ldo + j] = v;
        }
    }
}

__device__ __forceinline__ void layer_norm_res(float* __restrict__ h,
                                               const float* __restrict__ g, int ldg,
                                               const float* __restrict__ sc,
                                               const float* __restrict__ bt,
                                               int lane, int wid)
{
    for (int t = wid; t < 65; t += 16) {
        float v[4];
        float s = 0.f;
#pragma unroll
        for (int i = 0; i < 4; ++i) {
            int c = lane + 32 * i;
            v[i] = h[t * LDH + c] + g[t * ldg + c];
            s += v[i];
        }
        s = warp_sum(s);
        float mean = s * 0.0078125f;
        float var = 0.f;
#pragma unroll
        for (int i = 0; i < 4; ++i) { float dd = v[i] - mean; var = fmaf(dd, dd, var); }
        var = warp_sum(var) * 0.0078125f;
        float rs = rsqrtf(var + 1e-5f);
#pragma unroll
        for (int i = 0; i < 4; ++i) {
            int c = lane + 32 * i;
            h[t * LDH + c] = (v[i] - mean) * rs * sc[c] + bt[c];
        }
    }
}

__global__ void __launch_bounds__(TPB, 1)
vit_kernel(const float* __restrict__ x,
           const float* __restrict__ patch_w,
           const float* __restrict__ patch_b,
           const float* __restrict__ cls_token,
           const float* __restrict__ pos_embed,
           const float* __restrict__ qkv_b,
           const float* __restrict__ out_b,
           const float* __restrict__ ln1_s,
           const float* __restrict__ ln1_b,
           const float* __restrict__ ln2_s,
           const float* __restrict__ ln2_b,
           const float* __restrict__ ff1_b,
           const float* __restrict__ ff2_b,
           const float* __restrict__ qr1_w,
           const float* __restrict__ qr1_b,
           const float* __restrict__ qr2_w,
           const float* __restrict__ qr2_b,
           const float* __restrict__ q_weights,
           const float* __restrict__ clf_w,
           const float* __restrict__ clf_b,
           float* __restrict__ y)
{
    extern __shared__ float sm[];
    float* h    = sm + OFF_H;
    float* S    = sm + OFF_S;
    float* kT   = sm + OFF_A;     // aliases A-stage (dead during attention)
    float* G    = sm + OFF_B;     // aliases B-stage (dead at epilogue time)
    char*  Ast  = (char*)(sm + OFF_A);
    float* Bstf = sm + OFF_B;

    const int tid  = threadIdx.x;
    const int lane = tid & 31;
    const int wid  = tid >> 5;
    const int b    = blockIdx.x;

    const u32 aB = smem_u32(sm + OFF_A);
    const u32 bB = smem_u32(sm + OFF_B);

    // ---------------- patch embed (SIMT) ----------------
    const float* xb = x + (size_t)b * 3072;
    for (int i = tid; i < 3072; i += TPB) Bstf[i] = xb[i];
    for (int i = tid; i < 6144; i += TPB) {          // patch_w [d][ck] -> S[ck][d]
        int d = i / 48, ck = i - d * 48;
        S[ck * 128 + d] = patch_w[i];
    }
    __syncthreads();
    for (int idx = tid; idx < 8192; idx += TPB) {
        int tkn = idx >> 7, d = idx & 127;
        int pi = tkn >> 3, pj = tkn & 7;
        const float* xp = Bstf + pi * 128 + pj * 4;
        float acc = patch_b[d];
#pragma unroll
        for (int c = 0; c < 3; ++c)
#pragma unroll
            for (int p = 0; p < 4; ++p)
#pragma unroll
                for (int q = 0; q < 4; ++q)
                    acc = fmaf(xp[c * 1024 + p * 32 + q], S[(c * 16 + p * 4 + q) * 128 + d], acc);
        h[(1 + tkn) * LDH + d] = acc + pos_embed[(1 + tkn) * 128 + d];
    }
    for (int d = tid; d < 128; d += TPB) h[d] = cls_token[d] + pos_embed[d];
    __syncthreads();

    const float SCALE = 0.17677669529663687f;
    float d_[4][4], g_[8];

    for (int li = 0; li < 4; ++li) {
        const __nv_bfloat16 (*wt)[2][128 * 136] = g_wsplit[li];
        const float* qb = qkv_b + li * 384;

        // ---------- QKV (order: Q, V, K — K last so kT can overwrite A-stage) ----------
        convert_A(h, LDH, Ast, tid);
        stage_B(wt[0][0], Bstf, tid);
        __syncthreads();
        zero_acc(d_, g_); gemm_tile(h, LDH, aB, bB, Bstf, d_, g_, lane, wid);
        __syncthreads();
        stage_B(wt[1][0], Bstf, tid);                       // V weights
        epilogue<0, 0>(d_, g_, qb, S, LDS_, lane, wid);     // Q -> S[:,0:128]
        __syncthreads();
        zero_acc(d_, g_); gemm_tile(h, LDH, aB, bB, Bstf, d_, g_, lane, wid);
        __syncthreads();
        stage_B(wt[2][0], Bstf, tid);                       // K weights
        epilogue<0, 0>(d_, g_, qb + 256, S + 134, LDS_, lane, wid);  // V
        __syncthreads();
        zero_acc(d_, g_); gemm_tile(h, LDH, aB, bB, Bstf, d_, g_, lane, wid);
        __syncthreads();
        epilogue<0, 1>(d_, g_, qb + 128, kT, LDKT, lane, wid);       // K^T over A-stage
        __syncthreads();

        // ---------- attention (SIMT; per-warp float4 scratch in B-stage) ----------
        {
            float* scr = Bstf + wid * 408;        // q4 [32][4] | pw4 [65][4]
            float* q4  = scr;
            float* pw4 = scr + 128;
            for (int u = wid; u < 68; u += 16) {
                int hd = u & 3, tt = u >> 2;
                int ho = hd << 5;
                int t0 = tt << 2;
                const float* qrow = S + t0 * LDS_ + ho;
                const float* kb   = kT + ho * LDKT;

                // transpose q into float4 rows: q4[k] = {q[t0+0..3][ho+k]}
                float qv0 = qrow[lane];
                float qv1 = qrow[LDS_ + lane];
                float qv2 = qrow[2 * LDS_ + lane];
                float qv3 = qrow[3 * LDS_ + lane];
                *reinterpret_cast<float4*>(q4 + lane * 4) = make_float4(qv0, qv1, qv2, qv3);
                __syncwarp();

                float a0[4], a1[4], a64[4];
#pragma unroll
                for (int i = 0; i < 4; ++i) { a0[i] = 0.f; a1[i] = 0.f; a64[i] = 0.f; }
#pragma unroll 8
                for (int k = 0; k < 32; ++k) {
                    float4 qk = ld4(q4 + k * 4);
                    float k0  = kb[k * LDKT + lane];
                    float k1  = kb[k * LDKT + 32 + lane];
                    float k64 = kb[k * LDKT + 64];
                    a0[0] = fmaf(qk.x, k0, a0[0]); a0[1] = fmaf(qk.y, k0, a0[1]);
                    a0[2] = fmaf(qk.z, k0, a0[2]); a0[3] = fmaf(qk.w, k0, a0[3]);
                    a1[0] = fmaf(qk.x, k1, a1[0]); a1[1] = fmaf(qk.y, k1, a1[1]);
                    a1[2] = fmaf(qk.z, k1, a1[2]); a1[3] = fmaf(qk.w, k1, a1[3]);
                    a64[0] = fmaf(qk.x, k64, a64[0]); a64[1] = fmaf(qk.y, k64, a64[1]);
                    a64[2] = fmaf(qk.z, k64, a64[2]); a64[3] = fmaf(qk.w, k64, a64[3]);
                }

                float p0[4], p1[4], p64[4];
#pragma unroll
                for (int i = 0; i < 4; ++i) {
                    float v0 = a0[i] * SCALE, v1 = a1[i] * SCALE, v2 = a64[i] * SCALE;
                    float m = fmaxf(warp_max(fmaxf(v0, v1)), v2);   // v2 uniform across lanes
                    float e0 = __expf(v0 - m), e1 = __expf(v1 - m), e2 = __expf(v2 - m);
                    float ssum = warp_sum(e0 + e1) + e2;
                    float inv = 1.f / ssum;
                    p0[i] = e0 * inv; p1[i] = e1 * inv; p64[i] = e2 * inv;
                }
                // transpose probs: pw4[u] = {p[t0+0..3][u]}
                *reinterpret_cast<float4*>(pw4 + lane * 4) =
                    make_float4(p0[0], p0[1], p0[2], p0[3]);
                *reinterpret_cast<float4*>(pw4 + (32 + lane) * 4) =
                    make_float4(p1[0], p1[1], p1[2], p1[3]);
                if (lane == 0)
                    *reinterpret_cast<float4*>(pw4 + 256) =
                        make_float4(p64[0], p64[1], p64[2], p64[3]);
                __syncwarp();

                float oc[4] = {0.f, 0.f, 0.f, 0.f};
                const float* vb = S + 134 + ho + lane;
#pragma unroll 4
                for (int uu = 0; uu < 64; ++uu) {
                    float4 pv = ld4(pw4 + uu * 4);
                    float vv = vb[uu * LDS_];
                    oc[0] = fmaf(pv.x, vv, oc[0]);
                    oc[1] = fmaf(pv.y, vv, oc[1]);
                    oc[2] = fmaf(pv.z, vv, oc[2]);
                    oc[3] = fmaf(pv.w, vv, oc[3]);
                }
                {
                    float4 pv = ld4(pw4 + 256);
                    float vv = vb[64 * LDS_];
                    oc[0] = fmaf(pv.x, vv, oc[0]);
                    oc[1] = fmaf(pv.y, vv, oc[1]);
                    oc[2] = fmaf(pv.z, vv, oc[2]);
                    oc[3] = fmaf(pv.w, vv, oc[3]);
                }
#pragma unroll
                for (int i = 0; i < 4; ++i)
                    if (t0 + i < 65) S[(t0 + i) * LDS_ + ho + lane] = oc[i];
                __syncwarp();
            }
        }
        __syncthreads();

        // ---------- out-proj: S[:,0:128] -> G ----------
        convert_A(S, LDS_, Ast, tid);                       // overwrites kT (dead)
        stage_B(wt[3][0], Bstf, tid);                       // overwrites scratch (dead)
        __syncthreads();
        zero_acc(d_, g_); gemm_tile(S, LDS_, aB, bB, Bstf, d_, g_, lane, wid);
        __syncthreads();
        epilogue<0, 0>(d_, g_, out_b + li * 128, G, LDG_, lane, wid);   // G over B-stage
        __syncthreads();
        layer_norm_res(h, G, LDG_, ln1_s + li * 128, ln1_b + li * 128, lane, wid);
        __syncthreads();

        // ---------- FF1 (relu) ----------
        const float* f1b = ff1_b + li * 256;
        convert_A(h, LDH, Ast, tid);
        stage_B(wt[4][0], Bstf, tid);
        __syncthreads();
        zero_acc(d_, g_); gemm_tile(h, LDH, aB, bB, Bstf, d_, g_, lane, wid);
        __syncthreads();
        stage_B(wt[5][0], Bstf, tid);
        epilogue<1, 0>(d_, g_, f1b, S, LDS_, lane, wid);
        __syncthreads();
        zero_acc(d_, g_); gemm_tile(h, LDH, aB, bB, Bstf, d_, g_, lane, wid);
        __syncthreads();
        epilogue<1, 0>(d_, g_, f1b + 128, S + 134, LDS_, lane, wid);
        __syncthreads();

        // ---------- FF2 (K=256: two chunks, register accumulation) ----------
        convert_A(S, LDS_, Ast, tid);
        stage_B(wt[6][0], Bstf, tid);
        __syncthreads();
        zero_acc(d_, g_); gemm_tile(S, LDS_, aB, bB, Bstf, d_, g_, lane, wid);
        __syncthreads();
        convert_A(S + 134, LDS_, Ast, tid);
        stage_B(wt[7][0], Bstf, tid);
        __syncthreads();
        gemm_tile(S + 134, LDS_, aB, bB, Bstf, d_, g_, lane, wid);
        __syncthreads();
        epilogue<0, 0>(d_, g_, ff2_b + li * 128, G, LDG_, lane, wid);
        __syncthreads();
        layer_norm_res(h, G, LDG_, ln2_s + li * 128, ln2_b + li * 128, lane, wid);
        __syncthreads();
    }

    // ---------------- readout head (warp 0) ----------------
    if (wid == 0) {
        float accq = qr1_b[lane];
        const float* wr = qr1_w + lane * 128;
#pragma unroll 8
        for (int k = 0; k < 128; k += 4) {
            float4 hv = ld4(h + k);
            float4 wv = ld4(wr + k);
            accq = fmaf(hv.x, wv.x, accq);
            accq = fmaf(hv.y, wv.y, accq);
            accq = fmaf(hv.z, wv.z, accq);
            accq = fmaf(hv.w, wv.w, accq);
        }
        Bstf[lane] = fmaxf(accq, 0.f);
        __syncwarp();
        float qo[4];
#pragma unroll
        for (int m = 0; m < 4; ++m) {
            float s = qr2_b[m];
            for (int k = 0; k < 32; ++k) s = fmaf(Bstf[k], qr2_w[m * 32 + k], s);
            float qin = tanhf(s);
            qo[m] = cosf(qin) * cosf(q_weights[m]);
        }
        qo[1] *= qo[0]; qo[2] *= qo[1]; qo[3] *= qo[2];
        if (lane < 10) {
            float o = clf_b[lane];
            const float* cw = clf_w + lane * 132;
            for (int k = 0; k < 128; ++k) o = fmaf(h[k], cw[k], o);
#pragma unroll
            for (int m = 0; m < 4; ++m) o = fmaf(qo[m], cw[128 + m], o);
            y[b * 10 + lane] = o;
        }
    }
}

extern "C" void kernel_launch(void* const* d_in, const int* in_sizes, int n_in,
                              void* d_out, int out_size)
{
    const int B = in_sizes[0] / 3072;
    prep_kernel<<<1024, 512>>>(
        (const float*)d_in[5], (const float*)d_in[7],
        (const float*)d_in[13], (const float*)d_in[15]);
    cudaFuncSetAttribute(vit_kernel, cudaFuncAttributeMaxDynamicSharedMemorySize,
                         SMEM_FLOATS * (int)sizeof(float));
    vit_kernel<<<B, TPB, SMEM_FLOATS * sizeof(float)>>>(
        (const float*)d_in[0],  (const float*)d_in[1],  (const float*)d_in[2],
        (const float*)d_in[3],  (const float*)d_in[4],
        (const float*)d_in[6],  (const float*)d_in[8],
        (const float*)d_in[9],  (const float*)d_in[10], (const float*)d_in[11],
        (const float*)d_in[12], (const float*)d_in[14], (const float*)d_in[16],
        (const float*)d_in[17], (const float*)d_in[18], (const float*)d_in[19],
        (const float*)d_in[20], (const float*)d_in[21], (const float*)d_in[22],
        (const float*)d_in[23],
        (float*)d_out);
}

// round 16
// speedup vs baseline: 1.5014x; 1.5014x over previous
#include <cuda_runtime.h>
#include <cuda_bf16.h>
#include <math.h>
#include <stdint.h>

typedef unsigned int u32;

#define TPB 512

// ---- smem layout (floats) ----
#define LDH   128
#define LDS_  266            // S row stride (q/ff1a 0..127 | v/ff1b 134..261)
#define LDKT  66
#define LDG_  134

#define OFF_H   0            // h [65][128] = 8320 f
#define OFF_S   8320         // S [65][266] = 17290 f
#define OFF_A   25612        // A-stage: Ah,Al 2x(65 rows x 272B) = 8840 f ; aliased: kT [128][66]
#define A_TERM_B 17680       // bytes per A term (65*272)
#define OFF_B   34452        // B-stage: Bh,Bl 2x(128 rows x 272B) = 17408 f ; aliased: G, scratch, x
#define B_TERM_B 34816       // bytes per B term (128*272)
#define SMEM_FLOATS 51860    // 207,440 B

// pre-split weights, padded-row layout identical to smem stage image:
// [layer][tile][hi/lo][n=128][136 bf16 (272B row, 128 data + pad)]
// tiles: 0=Wq 1=Wv 2=Wk 3=Wout 4=ff1a 5=ff1b 6=ff2c0 7=ff2c1
__device__ __align__(16) __nv_bfloat16 g_wsplit[4][8][2][128 * 136];

__global__ void prep_kernel(const float* __restrict__ qkv_w,
                            const float* __restrict__ out_w,
                            const float* __restrict__ ff1_w,
                            const float* __restrict__ ff2_w)
{
    int e = blockIdx.x * blockDim.x + threadIdx.x;     // 524288 total
    int layer = e >> 17;
    int r     = e & 131071;
    int tile  = r >> 14;
    int r2    = r & 16383;
    int n = r2 >> 7, k = r2 & 127;
    float w;
    if (tile == 0)      w = qkv_w[layer * 49152 + n * 128 + k];                    // Wq
    else if (tile == 1) w = qkv_w[layer * 49152 + (256 + n) * 128 + k];            // Wv
    else if (tile == 2) w = qkv_w[layer * 49152 + (128 + n) * 128 + k];            // Wk
    else if (tile == 3) w = out_w[layer * 16384 + n * 128 + k];
    else if (tile < 6)  w = ff1_w[layer * 32768 + ((tile - 4) * 128 + n) * 128 + k];
    else                w = ff2_w[layer * 32768 + n * 256 + (tile - 6) * 128 + k];
    __nv_bfloat16 hi = __float2bfloat16_rn(w);
    __nv_bfloat16 lo = __float2bfloat16_rn(w - __bfloat162float(hi));
    g_wsplit[layer][tile][0][n * 136 + k] = hi;
    g_wsplit[layer][tile][1][n * 136 + k] = lo;
}

// ---- helpers ----
__device__ __forceinline__ u32 smem_u32(const void* p) {
    u32 a;
    asm("{ .reg .u64 t; cvta.to.shared.u64 t, %1; cvt.u32.u64 %0, t; }" : "=r"(a) : "l"(p));
    return a;
}
__device__ __forceinline__ float4 ld4(const float* p) { return *reinterpret_cast<const float4*>(p); }
__device__ __forceinline__ float warp_sum(float v) {
#pragma unroll
    for (int o = 16; o > 0; o >>= 1) v += __shfl_xor_sync(0xffffffffu, v, o);
    return v;
}
__device__ __forceinline__ float warp_max(float v) {
#pragma unroll
    for (int o = 16; o > 0; o >>= 1) v = fmaxf(v, __shfl_xor_sync(0xffffffffu, v, o));
    return v;
}
__device__ __forceinline__ void ldm4(u32* r, u32 addr) {
    asm volatile("ldmatrix.sync.aligned.m8n8.x4.shared.b16 {%0,%1,%2,%3}, [%4];"
                 : "=r"(r[0]), "=r"(r[1]), "=r"(r[2]), "=r"(r[3]) : "r"(addr));
}
__device__ __forceinline__ void mma16816(float* d, const u32* a, u32 b0, u32 b1) {
    asm volatile("mma.sync.aligned.m16n8k16.row.col.f32.bf16.bf16.f32 "
                 "{%0,%1,%2,%3}, {%4,%5,%6,%7}, {%8,%9}, {%0,%1,%2,%3};"
                 : "+f"(d[0]), "+f"(d[1]), "+f"(d[2]), "+f"(d[3])
                 : "r"(a[0]), "r"(a[1]), "r"(a[2]), "r"(a[3]), "r"(b0), "r"(b1));
}

// stage Bh+Bl (contiguous 69632 B = 4352 uint4) from pre-split global into B region
__device__ __forceinline__ void stage_B(const __nv_bfloat16* __restrict__ src,
                                        float* __restrict__ Breg, int tid)
{
    const uint4* s = reinterpret_cast<const uint4*>(src);
    uint4*       d = reinterpret_cast<uint4*>(Breg);
    for (int i = tid; i < 4352; i += TPB) d[i] = s[i];
}

// convert A (65 x 128 fp32, row stride lda) -> Ah + Al bf16 padded tiles
__device__ __forceinline__ void convert_A(const float* __restrict__ src, int lda,
                                          char* __restrict__ Ast, int tid)
{
    for (int idx = tid; idx < 4160; idx += TPB) {     // 65 rows * 64 k-pairs
        int row = idx >> 6, kp = idx & 63;
        float2 v = *reinterpret_cast<const float2*>(src + row * lda + kp * 2);
        __nv_bfloat16 h0 = __float2bfloat16_rn(v.x);
        __nv_bfloat16 h1 = __float2bfloat16_rn(v.y);
        __nv_bfloat16 l0 = __float2bfloat16_rn(v.x - __bfloat162float(h0));
        __nv_bfloat16 l1 = __float2bfloat16_rn(v.y - __bfloat162float(h1));
        char* p = Ast + row * 272 + kp * 4;
        *reinterpret_cast<u32*>(p) =
            ((u32)__bfloat16_as_ushort(h1) << 16) | (u32)__bfloat16_as_ushort(h0);
        *reinterpret_cast<u32*>(p + A_TERM_B) =
            ((u32)__bfloat16_as_ushort(l1) << 16) | (u32)__bfloat16_as_ushort(l0);
    }
}

// 3-term 65x128x128 GEMM tile: rows 0-63 via HMMA (warp m16 x n32), row 64 via gemv.
// R14 form: per term, per kstep: 3 ldm4 + 4 MMAs (low register pressure).
__device__ void gemm_tile(const float* __restrict__ Afp, int lda,
                          u32 aB, u32 bB, const float* __restrict__ smB,
                          float (&d)[4][4], float (&g)[8], int lane, int wid)
{
    const int mg = wid >> 2, ng = wid & 3;
    const u32 aAddr = aB + (u32)((mg * 16 + (lane & 15)) * 272 + ((lane >> 4) << 4));
    const u32 bAddr = bB + (u32)((ng * 32 + ((lane >> 4) << 3) + (lane & 7)) * 272
                                 + (((lane >> 3) & 1) << 4));
#pragma unroll
    for (int term = 0; term < 3; ++term) {
        const u32 aA = aAddr + (term == 2 ? (u32)A_TERM_B : 0u);
        const u32 bA = bAddr + (term == 1 ? (u32)B_TERM_B : 0u);
#pragma unroll
        for (int ks = 0; ks < 8; ++ks) {
            u32 a[4], p[4], q[4];
            ldm4(a, aA + ks * 32);
            ldm4(p, bA + ks * 32);
            ldm4(q, bA + 16 * 272 + ks * 32);
            mma16816(d[0], a, p[0], p[1]);
            mma16816(d[1], a, p[2], p[3]);
            mma16816(d[2], a, q[0], q[1]);
            mma16816(d[3], a, q[2], q[3]);
        }
    }
    // row 64 gemv (B = hi + lo)
    const float* A64 = Afp + 64 * lda;
    const __nv_bfloat16* BH = reinterpret_cast<const __nv_bfloat16*>(smB);
    const __nv_bfloat16* BL = reinterpret_cast<const __nv_bfloat16*>(
                                  reinterpret_cast<const char*>(smB) + B_TERM_B);
    float a0 = A64[lane], a1 = A64[lane + 32], a2 = A64[lane + 64], a3 = A64[lane + 96];
#pragma unroll
    for (int jj = 0; jj < 8; ++jj) {
        int n = wid * 8 + jj;
        const __nv_bfloat16* rh = BH + n * 136;
        const __nv_bfloat16* rl = BL + n * 136;
        float s;
        s = fmaf(a0, __bfloat162float(rh[lane])      + __bfloat162float(rl[lane]),      0.f);
        s = fmaf(a1, __bfloat162float(rh[lane + 32]) + __bfloat162float(rl[lane + 32]), s);
        s = fmaf(a2, __bfloat162float(rh[lane + 64]) + __bfloat162float(rl[lane + 64]), s);
        s = fmaf(a3, __bfloat162float(rh[lane + 96]) + __bfloat162float(rl[lane + 96]), s);
        g[jj] += s;
    }
}

__device__ __forceinline__ void zero_acc(float (&d)[4][4], float (&g)[8]) {
#pragma unroll
    for (int i = 0; i < 4; ++i)
#pragma unroll
        for (int j = 0; j < 4; ++j) d[i][j] = 0.f;
#pragma unroll
    for (int j = 0; j < 8; ++j) g[j] = 0.f;
}

template<int RELU, int TRANS>
__device__ void epilogue(float (&d)[4][4], float (&g)[8],
                         const float* __restrict__ bias,
                         float* __restrict__ Out, int ldo, int lane, int wid)
{
    const int mg = wid >> 2, ng = wid & 3;
    const int r0 = mg * 16 + (lane >> 2);
    const int c0 = ng * 32 + (lane & 3) * 2;
#pragma unroll
    for (int nt = 0; nt < 4; ++nt) {
        int c = c0 + nt * 8;
        float b0 = bias[c], b1 = bias[c + 1];
        float v0 = d[nt][0] + b0, v1 = d[nt][1] + b1;
        float v2 = d[nt][2] + b0, v3 = d[nt][3] + b1;
        if (RELU) {
            v0 = fmaxf(v0, 0.f); v1 = fmaxf(v1, 0.f);
            v2 = fmaxf(v2, 0.f); v3 = fmaxf(v3, 0.f);
        }
        if (TRANS) {
            Out[c * ldo + r0]           = v0;
            Out[(c + 1) * ldo + r0]     = v1;
            Out[c * ldo + r0 + 8]       = v2;
            Out[(c + 1) * ldo + r0 + 8] = v3;
        } else {
            Out[r0 * ldo + c]           = v0;
            Out[r0 * ldo + c + 1]       = v1;
            Out[(r0 + 8) * ldo + c]     = v2;
            Out[(r0 + 8) * ldo + c + 1] = v3;
        }
    }
#pragma unroll
    for (int jj = 0; jj < 8; ++jj) {
        float s = warp_sum(g[jj]);
        if (lane == jj) {
            int j = wid * 8 + jj;
            float v = s + bias[j];
            if (RELU) v = fmaxf(v, 0.f);
            if (TRANS) Out[j * ldo + 64] = v;
            else       Out[64 * ldo + j] = v;
        }
    }
}

__device__ __forceinline__ void layer_norm_res(float* __restrict__ h,
                                               const float* __restrict__ g, int ldg,
                                               const float* __restrict__ sc,
                                               const float* __restrict__ bt,
                                               int lane, int wid)
{
    for (int t = wid; t < 65; t += 16) {
        float v[4];
        float s = 0.f;
#pragma unroll
        for (int i = 0; i < 4; ++i) {
            int c = lane + 32 * i;
            v[i] = h[t * LDH + c] + g[t * ldg + c];
            s += v[i];
        }
        s = warp_sum(s);
        float mean = s * 0.0078125f;
        float var = 0.f;
#pragma unroll
        for (int i = 0; i < 4; ++i) { float dd = v[i] - mean; var = fmaf(dd, dd, var); }
        var = warp_sum(var) * 0.0078125f;
        float rs = rsqrtf(var + 1e-5f);
#pragma unroll
        for (int i = 0; i < 4; ++i) {
            int c = lane + 32 * i;
            h[t * LDH + c] = (v[i] - mean) * rs * sc[c] + bt[c];
        }
    }
}

__global__ void __launch_bounds__(TPB, 1)
vit_kernel(const float* __restrict__ x,
           const float* __restrict__ patch_w,
           const float* __restrict__ patch_b,
           const float* __restrict__ cls_token,
           const float* __restrict__ pos_embed,
           const float* __restrict__ qkv_b,
           const float* __restrict__ out_b,
           const float* __restrict__ ln1_s,
           const float* __restrict__ ln1_b,
           const float* __restrict__ ln2_s,
           const float* __restrict__ ln2_b,
           const float* __restrict__ ff1_b,
           const float* __restrict__ ff2_b,
           const float* __restrict__ qr1_w,
           const float* __restrict__ qr1_b,
           const float* __restrict__ qr2_w,
           const float* __restrict__ qr2_b,
           const float* __restrict__ q_weights,
           const float* __restrict__ clf_w,
           const float* __restrict__ clf_b,
           float* __restrict__ y)
{
    extern __shared__ float sm[];
    float* h    = sm + OFF_H;
    float* S    = sm + OFF_S;
    float* kT   = sm + OFF_A;     // aliases A-stage (dead during attention)
    float* G    = sm + OFF_B;     // aliases B-stage (dead at epilogue time)
    char*  Ast  = (char*)(sm + OFF_A);
    float* Bstf = sm + OFF_B;

    const int tid  = threadIdx.x;
    const int lane = tid & 31;
    const int wid  = tid >> 5;
    const int b    = blockIdx.x;

    const u32 aB = smem_u32(sm + OFF_A);
    const u32 bB = smem_u32(sm + OFF_B);

    // ---------------- patch embed (SIMT) ----------------
    const float* xb = x + (size_t)b * 3072;
    for (int i = tid; i < 3072; i += TPB) Bstf[i] = xb[i];
    for (int i = tid; i < 6144; i += TPB) {          // patch_w [d][ck] -> S[ck][d]
        int d = i / 48, ck = i - d * 48;
        S[ck * 128 + d] = patch_w[i];
    }
    __syncthreads();
    for (int idx = tid; idx < 8192; idx += TPB) {
        int tkn = idx >> 7, d = idx & 127;
        int pi = tkn >> 3, pj = tkn & 7;
        const float* xp = Bstf + pi * 128 + pj * 4;
        float acc = patch_b[d];
#pragma unroll
        for (int c = 0; c < 3; ++c)
#pragma unroll
            for (int p = 0; p < 4; ++p)
#pragma unroll
                for (int q = 0; q < 4; ++q)
                    acc = fmaf(xp[c * 1024 + p * 32 + q], S[(c * 16 + p * 4 + q) * 128 + d], acc);
        h[(1 + tkn) * LDH + d] = acc + pos_embed[(1 + tkn) * 128 + d];
    }
    for (int d = tid; d < 128; d += TPB) h[d] = cls_token[d] + pos_embed[d];
    __syncthreads();

    const float SCALE = 0.17677669529663687f;
    float d_[4][4], g_[8];

    for (int li = 0; li < 4; ++li) {
        const __nv_bfloat16 (*wt)[2][128 * 136] = g_wsplit[li];
        const float* qb = qkv_b + li * 384;

        // ---------- QKV (order: Q, V, K — K last so kT can overwrite A-stage) ----------
        convert_A(h, LDH, Ast, tid);
        stage_B(wt[0][0], Bstf, tid);
        __syncthreads();
        zero_acc(d_, g_); gemm_tile(h, LDH, aB, bB, Bstf, d_, g_, lane, wid);
        __syncthreads();
        stage_B(wt[1][0], Bstf, tid);                       // V weights
        epilogue<0, 0>(d_, g_, qb, S, LDS_, lane, wid);     // Q -> S[:,0:128]
        __syncthreads();
        zero_acc(d_, g_); gemm_tile(h, LDH, aB, bB, Bstf, d_, g_, lane, wid);
        __syncthreads();
        stage_B(wt[2][0], Bstf, tid);                       // K weights
        epilogue<0, 0>(d_, g_, qb + 256, S + 134, LDS_, lane, wid);  // V
        __syncthreads();
        zero_acc(d_, g_); gemm_tile(h, LDH, aB, bB, Bstf, d_, g_, lane, wid);
        __syncthreads();
        epilogue<0, 1>(d_, g_, qb + 128, kT, LDKT, lane, wid);       // K^T over A-stage
        __syncthreads();

        // ---------- attention (SIMT; per-warp float4 scratch in B-stage) ----------
        {
            float* scr = Bstf + wid * 408;        // q4 [32][4] | pw4 [65][4]
            float* q4  = scr;
            float* pw4 = scr + 128;
            for (int u = wid; u < 68; u += 16) {
                int hd = u & 3, tt = u >> 2;
                int ho = hd << 5;
                int t0 = tt << 2;
                const float* qrow = S + t0 * LDS_ + ho;
                const float* kb   = kT + ho * LDKT;

                // transpose q into float4 rows: q4[k] = {q[t0+0..3][ho+k]}
                float qv0 = qrow[lane];
                float qv1 = qrow[LDS_ + lane];
                float qv2 = qrow[2 * LDS_ + lane];
                float qv3 = qrow[3 * LDS_ + lane];
                *reinterpret_cast<float4*>(q4 + lane * 4) = make_float4(qv0, qv1, qv2, qv3);
                __syncwarp();

                float a0[4], a1[4], a64[4];
#pragma unroll
                for (int i = 0; i < 4; ++i) { a0[i] = 0.f; a1[i] = 0.f; a64[i] = 0.f; }
#pragma unroll 8
                for (int k = 0; k < 32; ++k) {
                    float4 qk = ld4(q4 + k * 4);
                    float k0  = kb[k * LDKT + lane];
                    float k1  = kb[k * LDKT + 32 + lane];
                    float k64 = kb[k * LDKT + 64];
                    a0[0] = fmaf(qk.x, k0, a0[0]); a0[1] = fmaf(qk.y, k0, a0[1]);
                    a0[2] = fmaf(qk.z, k0, a0[2]); a0[3] = fmaf(qk.w, k0, a0[3]);
                    a1[0] = fmaf(qk.x, k1, a1[0]); a1[1] = fmaf(qk.y, k1, a1[1]);
                    a1[2] = fmaf(qk.z, k1, a1[2]); a1[3] = fmaf(qk.w, k1, a1[3]);
                    a64[0] = fmaf(qk.x, k64, a64[0]); a64[1] = fmaf(qk.y, k64, a64[1]);
                    a64[2] = fmaf(qk.z, k64, a64[2]); a64[3] = fmaf(qk.w, k64, a64[3]);
                }

                float p0[4], p1[4], p64[4];
#pragma unroll
                for (int i = 0; i < 4; ++i) {
                    float v0 = a0[i] * SCALE, v1 = a1[i] * SCALE, v2 = a64[i] * SCALE;
                    float m = fmaxf(warp_max(fmaxf(v0, v1)), v2);   // v2 uniform across lanes
                    float e0 = __expf(v0 - m), e1 = __expf(v1 - m), e2 = __expf(v2 - m);
                    float ssum = warp_sum(e0 + e1) + e2;
                    float inv = 1.f / ssum;
                    p0[i] = e0 * inv; p1[i] = e1 * inv; p64[i] = e2 * inv;
                }
                // transpose probs: pw4[u] = {p[t0+0..3][u]}
                *reinterpret_cast<float4*>(pw4 + lane * 4) =
                    make_float4(p0[0], p0[1], p0[2], p0[3]);
                *reinterpret_cast<float4*>(pw4 + (32 + lane) * 4) =
                    make_float4(p1[0], p1[1], p1[2], p1[3]);
                if (lane == 0)
                    *reinterpret_cast<float4*>(pw4 + 256) =
                        make_float4(p64[0], p64[1], p64[2], p64[3]);
                __syncwarp();

                float oc[4] = {0.f, 0.f, 0.f, 0.f};
                const float* vb = S + 134 + ho + lane;
#pragma unroll 4
                for (int uu = 0; uu < 64; ++uu) {
                    float4 pv = ld4(pw4 + uu * 4);
                    float vv = vb[uu * LDS_];
                    oc[0] = fmaf(pv.x, vv, oc[0]);
                    oc[1] = fmaf(pv.y, vv, oc[1]);
                    oc[2] = fmaf(pv.z, vv, oc[2]);
                    oc[3] = fmaf(pv.w, vv, oc[3]);
                }
                {
                    float4 pv = ld4(pw4 + 256);
                    float vv = vb[64 * LDS_];
                    oc[0] = fmaf(pv.x, vv, oc[0]);
                    oc[1] = fmaf(pv.y, vv, oc[1]);
                    oc[2] = fmaf(pv.z, vv, oc[2]);
                    oc[3] = fmaf(pv.w, vv, oc[3]);
                }
#pragma unroll
                for (int i = 0; i < 4; ++i)
                    if (t0 + i < 65) S[(t0 + i) * LDS_ + ho + lane] = oc[i];
                __syncwarp();
            }
        }
        __syncthreads();

        // ---------- out-proj: S[:,0:128] -> G ----------
        convert_A(S, LDS_, Ast, tid);                       // overwrites kT (dead)
        stage_B(wt[3][0], Bstf, tid);                       // overwrites scratch (dead)
        __syncthreads();
        zero_acc(d_, g_); gemm_tile(S, LDS_, aB, bB, Bstf, d_, g_, lane, wid);
        __syncthreads();
        epilogue<0, 0>(d_, g_, out_b + li * 128, G, LDG_, lane, wid);   // G over B-stage
        __syncthreads();
        layer_norm_res(h, G, LDG_, ln1_s + li * 128, ln1_b + li * 128, lane, wid);
        __syncthreads();

        // ---------- FF1 (relu) ----------
        const float* f1b = ff1_b + li * 256;
        convert_A(h, LDH, Ast, tid);
        stage_B(wt[4][0], Bstf, tid);
        __syncthreads();
        zero_acc(d_, g_); gemm_tile(h, LDH, aB, bB, Bstf, d_, g_, lane, wid);
        __syncthreads();
        stage_B(wt[5][0], Bstf, tid);
        epilogue<1, 0>(d_, g_, f1b, S, LDS_, lane, wid);
        __syncthreads();
        zero_acc(d_, g_); gemm_tile(h, LDH, aB, bB, Bstf, d_, g_, lane, wid);
        __syncthreads();
        epilogue<1, 0>(d_, g_, f1b + 128, S + 134, LDS_, lane, wid);
        __syncthreads();

        // ---------- FF2 (K=256: two chunks, register accumulation) ----------
        convert_A(S, LDS_, Ast, tid);
        stage_B(wt[6][0], Bstf, tid);
        __syncthreads();
        zero_acc(d_, g_); gemm_tile(S, LDS_, aB, bB, Bstf, d_, g_, lane, wid);
        __syncthreads();
        convert_A(S + 134, LDS_, Ast, tid);
        stage_B(wt[7][0], Bstf, tid);
        __syncthreads();
        gemm_tile(S + 134, LDS_, aB, bB, Bstf, d_, g_, lane, wid);
        __syncthreads();
        epilogue<0, 0>(d_, g_, ff2_b + li * 128, G, LDG_, lane, wid);
        __syncthreads();
        layer_norm_res(h, G, LDG_, ln2_s + li * 128, ln2_b + li * 128, lane, wid);
        __syncthreads();
    }

    // ---------------- readout head (warp 0) ----------------
    if (wid == 0) {
        float accq = qr1_b[lane];
        const float* wr = qr1_w + lane * 128;
#pragma unroll 8
        for (int k = 0; k < 128; k += 4) {
            float4 hv = ld4(h + k);
            float4 wv = ld4(wr + k);
            accq = fmaf(hv.x, wv.x, accq);
            accq = fmaf(hv.y, wv.y, accq);
            accq = fmaf(hv.z, wv.z, accq);
            accq = fmaf(hv.w, wv.w, accq);
        }
        Bstf[lane] = fmaxf(accq, 0.f);
        __syncwarp();
        float qo[4];
#pragma unroll
        for (int m = 0; m < 4; ++m) {
            float s = qr2_b[m];
            for (int k = 0; k < 32; ++k) s = fmaf(Bstf[k], qr2_w[m * 32 + k], s);
            float qin = tanhf(s);
            qo[m] = cosf(qin) * cosf(q_weights[m]);
        }
        qo[1] *= qo[0]; qo[2] *= qo[1]; qo[3] *= qo[2];
        if (lane < 10) {
            float o = clf_b[lane];
            const float* cw = clf_w + lane * 132;
            for (int k = 0; k < 128; ++k) o = fmaf(h[k], cw[k], o);
#pragma unroll
            for (int m = 0; m < 4; ++m) o = fmaf(qo[m], cw[128 + m], o);
            y[b * 10 + lane] = o;
        }
    }
}

extern "C" void kernel_launch(void* const* d_in, const int* in_sizes, int n_in,
                              void* d_out, int out_size)
{
    const int B = in_sizes[0] / 3072;
    prep_kernel<<<1024, 512>>>(
        (const float*)d_in[5], (const float*)d_in[7],
        (const float*)d_in[13], (const float*)d_in[15]);
    cudaFuncSetAttribute(vit_kernel, cudaFuncAttributeMaxDynamicSharedMemorySize,
                         SMEM_FLOATS * (int)sizeof(float));
    vit_kernel<<<B, TPB, SMEM_FLOATS * sizeof(float)>>>(
        (const float*)d_in[0],  (const float*)d_in[1],  (const float*)d_in[2],
        (const float*)d_in[3],  (const float*)d_in[4],
        (const float*)d_in[6],  (const float*)d_in[8],
        (const float*)d_in[9],  (const float*)d_in[10], (const float*)d_in[11],
        (const float*)d_in[12], (const float*)d_in[14], (const float*)d_in[16],
        (const float*)d_in[17], (const float*)d_in[18], (const float*)d_in[19],
        (const float*)d_in[20], (const float*)d_in[21], (const float*)d_in[22],
        (const float*)d_in[23],
        (float*)d_out);
}